// round 7
// baseline (speedup 1.0000x reference)
#include <cuda_runtime.h>

#define NB   8
#define NH   32
#define NW   32
#define NC   32
#define HO   30
#define WO   30
#define NF   64

// Exact prune threshold: max over filters of (max_k w - min_k w).
__device__ float g_T;

// 1024 threads: 16 k-chunks x 64 filters, 18 independent L2 loads each.
__global__ __launch_bounds__(1024) void trop_T_kernel(const float* __restrict__ w) {
    __shared__ float smax[16][64];
    __shared__ float smin[16][64];
    int t = threadIdx.x;
    int f = t & 63;
    int chunk = t >> 6;
    int k0 = chunk * 18;
    float wmax = -1e30f, wmin = 1e30f;
#pragma unroll
    for (int q = 0; q < 18; q++) {
        float v = w[(k0 + q) * NF + f];
        wmax = fmaxf(wmax, v);
        wmin = fminf(wmin, v);
    }
    smax[chunk][f] = wmax;
    smin[chunk][f] = wmin;
    __syncthreads();
    if (t < 32) {
        float a0 = -1e30f, b0 = 1e30f, a1 = -1e30f, b1 = 1e30f;
#pragma unroll
        for (int q = 0; q < 16; q++) {
            a0 = fmaxf(a0, smax[q][t]);      b0 = fminf(b0, smin[q][t]);
            a1 = fmaxf(a1, smax[q][t + 32]); b1 = fminf(b1, smin[q][t + 32]);
        }
        float r = fmaxf(a0 - b0, a1 - b1);
#pragma unroll
        for (int o = 16; o; o >>= 1)
            r = fmaxf(r, __shfl_xor_sync(0xffffffffu, r, o));
        if (t == 0) g_T = r;
    }
}

// Block = (b, ho, wgroup of 10 wo). 320 threads = 10 warps.
// Phase 2: warp = column (12 cols of 3 rows x 32 ch), ballot/popc compaction
// of per-column candidate lists (supersets of any window's candidates since
// winmax >= colmax). Phase 3: warp = position, consume 3 columns' lists.
__global__ __launch_bounds__(320) void trop_main_kernel(
    const float* __restrict__ x, const float* __restrict__ w,
    const float* __restrict__ bias, float* __restrict__ out) {

    int bx = blockIdx.x;
    int wg = bx % 3;
    int ho = (bx / 3) % HO;
    int b  = bx / (3 * HO);

    __shared__ float s[3][12 * NC];            // 4608 B patch
    __shared__ float colmax[12], colmin[12];
    __shared__ float cvh[12][96], cvl[12][96]; // candidate values (worst case)
    __shared__ unsigned char cih[12][96], cil[12][96]; // packed i*96+ch
    __shared__ int nhi[12], nlo[12];

    int t    = threadIdx.x;
    int wp   = t >> 5;
    int lane = t & 31;

    float T = g_T;
    float bias0 = bias[lane];
    float bias1 = bias[lane + 32];

    // Phase 1: contiguous float4 patch load (3 rows x 12 cols x 32 ch).
    if (t < 288) {
        int row = t / 96;
        int q   = t - row * 96;
        const float4* src = (const float4*)(x + ((b * NH + ho + row) * NW + wg * 10) * NC);
        ((float4*)s[row])[q] = src[q];
    }
    __syncthreads();

    // Phase 2: per-column reduce + lane-ordered compaction (deterministic).
    unsigned lt = (1u << lane) - 1u;
#pragma unroll
    for (int pass = 0; pass < 2; pass++) {
        int col = wp + pass * 10;             // warps 0,1 take cols 10,11 on pass 1
        if (col < 12) {
            float v0 = s[0][col * NC + lane];
            float v1 = s[1][col * NC + lane];
            float v2 = s[2][col * NC + lane];
            float cmx = fmaxf(fmaxf(v0, v1), v2);
            float cmn = fminf(fminf(v0, v1), v2);
#pragma unroll
            for (int o = 16; o; o >>= 1) {
                float a  = __shfl_xor_sync(0xffffffffu, cmx, o);
                float bq = __shfl_xor_sync(0xffffffffu, cmn, o);
                cmx = fmaxf(cmx, a);
                cmn = fminf(cmn, bq);
            }
            float th = cmx - T;
            float tl = cmn + T;
            unsigned m0 = __ballot_sync(0xffffffffu, v0 >= th);
            unsigned m1 = __ballot_sync(0xffffffffu, v1 >= th);
            unsigned m2 = __ballot_sync(0xffffffffu, v2 >= th);
            int h0 = __popc(m0), h1 = h0 + __popc(m1);
            if (v0 >= th) { int p = __popc(m0 & lt);      cvh[col][p] = v0; cih[col][p] = (unsigned char)lane; }
            if (v1 >= th) { int p = h0 + __popc(m1 & lt); cvh[col][p] = v1; cih[col][p] = (unsigned char)(96 + lane); }
            if (v2 >= th) { int p = h1 + __popc(m2 & lt); cvh[col][p] = v2; cih[col][p] = (unsigned char)(192 + lane); }
            unsigned n0 = __ballot_sync(0xffffffffu, v0 <= tl);
            unsigned n1 = __ballot_sync(0xffffffffu, v1 <= tl);
            unsigned n2 = __ballot_sync(0xffffffffu, v2 <= tl);
            int l0 = __popc(n0), l1 = l0 + __popc(n1);
            if (v0 <= tl) { int p = __popc(n0 & lt);      cvl[col][p] = v0; cil[col][p] = (unsigned char)lane; }
            if (v1 <= tl) { int p = l0 + __popc(n1 & lt); cvl[col][p] = v1; cil[col][p] = (unsigned char)(96 + lane); }
            if (v2 <= tl) { int p = l1 + __popc(n2 & lt); cvl[col][p] = v2; cil[col][p] = (unsigned char)(192 + lane); }
            if (lane == 0) {
                colmax[col] = cmx;
                colmin[col] = cmn;
                nhi[col] = h1 + __popc(m2);
                nlo[col] = l1 + __popc(n2);
            }
        }
    }
    __syncthreads();

    // Phase 3: warp = position. Tight window threshold trims the column
    // supersets; any superset containing the argmax gives the exact result.
    float wmx = fmaxf(fmaxf(colmax[wp], colmax[wp + 1]), colmax[wp + 2]);
    float wmn = fminf(fminf(colmin[wp], colmin[wp + 1]), colmin[wp + 2]);
    float th_hi = wmx - T;
    float th_lo = wmn + T;

    float amax0 = -1e30f, amax1 = -1e30f;
    float amin0 =  1e30f, amin1 =  1e30f;
#pragma unroll
    for (int j = 0; j < 3; j++) {
        int col = wp + j;
        int nh = nhi[col];
#pragma unroll 1
        for (int a = 0; a < nh; a++) {
            float pv = cvh[col][a];            // LDS broadcast, warp-uniform
            if (pv >= th_hi) {
                int k = (int)cih[col][a] + j * 32;  // i*96 + ch + j*32 = (i*3+j)*32+ch
                const float* wr = w + k * NF;
                amax0 = fmaxf(amax0, pv + wr[lane]);
                amax1 = fmaxf(amax1, pv + wr[lane + 32]);
            }
        }
        int nl = nlo[col];
#pragma unroll 1
        for (int a = 0; a < nl; a++) {
            float pv = cvl[col][a];
            if (pv <= th_lo) {
                int k = (int)cil[col][a] + j * 32;
                const float* wr = w + k * NF;
                amin0 = fminf(amin0, pv + wr[lane]);
                amin1 = fminf(amin1, pv + wr[lane + 32]);
            }
        }
    }

    // Phase 4: combine + bias, coalesced store.
    int wo  = wg * 10 + wp;
    int pos = (b * HO + ho) * WO + wo;
    out[pos * NF + lane]      = amax0 - amin0 + bias0;
    out[pos * NF + lane + 32] = amax1 - amin1 + bias1;
}

extern "C" void kernel_launch(void* const* d_in, const int* in_sizes, int n_in,
                              void* d_out, int out_size) {
    (void)in_sizes; (void)n_in; (void)out_size;
    const float* x    = (const float*)d_in[0];
    const float* w    = (const float*)d_in[1];
    const float* bias = (const float*)d_in[2];
    float* out = (float*)d_out;

    trop_T_kernel<<<1, 1024>>>(w);
    trop_main_kernel<<<NB * HO * 3, 320>>>(x, w, bias, out);
}

// round 8
// speedup vs baseline: 1.2418x; 1.2418x over previous
#include <cuda_runtime.h>

#define NB   8
#define NH   32
#define NW   32
#define NC   32
#define HO   30
#define WO   30
#define NF   64
#define NPOS (NB * HO * WO)   // 7200

// Exact prune threshold: max over filters of (max_k w - min_k w).
__device__ float g_T;

// 1024 threads: 16 k-chunks x 64 filters, 18 independent L2 loads each.
__global__ __launch_bounds__(1024) void trop_T_kernel(const float* __restrict__ w) {
    __shared__ float smax[16][64];
    __shared__ float smin[16][64];
    int t = threadIdx.x;
    int f = t & 63;
    int chunk = t >> 6;
    int k0 = chunk * 18;
    float wmax = -1e30f, wmin = 1e30f;
#pragma unroll
    for (int q = 0; q < 18; q++) {
        float v = w[(k0 + q) * NF + f];
        wmax = fmaxf(wmax, v);
        wmin = fminf(wmin, v);
    }
    smax[chunk][f] = wmax;
    smin[chunk][f] = wmin;
    __syncthreads();
    if (t < 32) {
        float a0 = -1e30f, b0 = 1e30f, a1 = -1e30f, b1 = 1e30f;
#pragma unroll
        for (int q = 0; q < 16; q++) {
            a0 = fmaxf(a0, smax[q][t]);      b0 = fminf(b0, smin[q][t]);
            a1 = fmaxf(a1, smax[q][t + 32]); b1 = fminf(b1, smin[q][t + 32]);
        }
        float r = fmaxf(a0 - b0, a1 - b1);
#pragma unroll
        for (int o = 16; o; o >>= 1)
            r = fmaxf(r, __shfl_xor_sync(0xffffffffu, r, o));
        if (t == 0) g_T = r;
    }
}

// Fully warp-autonomous: no shared memory, no __syncthreads. Each warp owns
// one output position; lane = channel. 9 coalesced LDGs bring the window
// straight to registers.
__global__ __launch_bounds__(128) void trop_main_kernel(
    const float* __restrict__ x, const float* __restrict__ w,
    const float* __restrict__ bias, float* __restrict__ out) {

    int g    = blockIdx.x * 4 + (threadIdx.x >> 5);   // global warp id = pos
    int lane = threadIdx.x & 31;

    int wo = g % WO;
    int r  = g / WO;
    int ho = r % HO;
    int b  = r / HO;

    // Phase 1: 9 independent coalesced loads (row i, col j) -> registers.
    const float* xp = x + (((b * NH + ho) * NW) + wo) * NC + lane;
    float v[9];
#pragma unroll
    for (int i = 0; i < 3; i++)
#pragma unroll
        for (int j = 0; j < 3; j++)
            v[i * 3 + j] = xp[i * (NW * NC) + j * NC];

    // Phase 2: interleaved SHFL butterfly for patch max/min.
    float mx = v[0], mn = v[0];
#pragma unroll
    for (int q = 1; q < 9; q++) {
        mx = fmaxf(mx, v[q]);
        mn = fminf(mn, v[q]);
    }
#pragma unroll
    for (int o = 16; o; o >>= 1) {
        float a  = __shfl_xor_sync(0xffffffffu, mx, o);
        float bq = __shfl_xor_sync(0xffffffffu, mn, o);
        mx = fmaxf(mx, a);
        mn = fminf(mn, bq);
    }

    // Phase 3: exact prune. k with p_k < max_p - T cannot achieve the
    // per-filter max for ANY filter (sym. min). Ballot + bit-iterate;
    // set max/min is order-independent -> deterministic.
    float T = g_T;
    float th_hi = mx - T;
    float th_lo = mn + T;

    float amax0 = -1e30f, amax1 = -1e30f;
    float amin0 =  1e30f, amin1 =  1e30f;

#pragma unroll
    for (int cell = 0; cell < 9; cell++) {
        float val = v[cell];
        unsigned mmax = __ballot_sync(0xffffffffu, val >= th_hi);
        unsigned mmin = __ballot_sync(0xffffffffu, val <= th_lo);
        while (mmax) {
            int c = __ffs(mmax) - 1; mmax &= mmax - 1;
            float pv = __shfl_sync(0xffffffffu, val, c);
            const float* wr = w + (cell * 32 + c) * NF;
            amax0 = fmaxf(amax0, pv + wr[lane]);
            amax1 = fmaxf(amax1, pv + wr[lane + 32]);
        }
        while (mmin) {
            int c = __ffs(mmin) - 1; mmin &= mmin - 1;
            float pv = __shfl_sync(0xffffffffu, val, c);
            const float* wr = w + (cell * 32 + c) * NF;
            amin0 = fminf(amin0, pv + wr[lane]);
            amin1 = fminf(amin1, pv + wr[lane + 32]);
        }
    }

    // Phase 4: combine + bias, coalesced store.
    out[g * NF + lane]      = amax0 - amin0 + bias[lane];
    out[g * NF + lane + 32] = amax1 - amin1 + bias[lane + 32];
}

extern "C" void kernel_launch(void* const* d_in, const int* in_sizes, int n_in,
                              void* d_out, int out_size) {
    (void)in_sizes; (void)n_in; (void)out_size;
    const float* x    = (const float*)d_in[0];
    const float* w    = (const float*)d_in[1];
    const float* bias = (const float*)d_in[2];
    float* out = (float*)d_out;

    trop_T_kernel<<<1, 1024>>>(w);
    trop_main_kernel<<<NPOS / 4, 128>>>(x, w, bias, out);
}